// round 11
// baseline (speedup 1.0000x reference)
#include <cuda_runtime.h>
#include <cuda_fp16.h>

#define B_   8
#define TGT  256
#define SRC  256
#define DM   512
#define LOGEPS (-18.420680743952367f)

#define APITCH 40    // halves; 80B rows -> conflict-free ldmatrix
#define BPITCH 136   // halves; 272B rows -> conflict-free ldmatrix.trans
#define STAGES 6
#define NITER 16
#define A_TILE_H 2560                 // 64*40 halves  = 5120 B
#define B_TILE_H 4352                 // 32*136 halves = 8704 B
#define STAGE_BYTES ((A_TILE_H + B_TILE_H) * 2)  // 13824
#define A_Z_H (32 * 16 * A_TILE_H)    // 1310720 halves per z
#define A_TOT_H (2 * A_Z_H)           // 2621440
#define B_Z_H (2 * 16 * B_TILE_H)     // 139264

// fused-kernel smem geometry (in 4-byte words)
#define EPW   36                       // et chunk row pitch: 8 uint4 + 1 pad
#define EBUF  (256 * EPW)              // 9216 words per et buffer
#define DTW   (8 * 132)                // dt tile: 8 rows x (128 half2 + 4 pad)
#define OPW   260                      // out-stage row pitch (floats)
#define FUSED_WORDS (2 * EBUF + DTW + 128 + 8 * OPW)  // 21696
#define FUSED_SMEM  (FUSED_WORDS * 4)                 // 86784 B

// scratch (no allocation allowed -> __device__ globals)
__device__ unsigned g_h16[1449984];              // tiled fp16 images (half2 words)
__device__ unsigned g_dt[B_ * TGT * (SRC / 2)];  // dec @ W1  [B,T,L] as half2
__device__ unsigned g_et[B_ * SRC * (SRC / 2)];  // enc @ W2  [B,S,L] as half2

__device__ __forceinline__ __half2 tanh2(__half2 x) {
    unsigned xi = *(unsigned*)&x, yi;
    asm("tanh.approx.f16x2 %0, %1;" : "=r"(yi) : "r"(xi));
    return *(__half2*)&yi;
}
__device__ __forceinline__ __half2 uh(unsigned u) { return *(__half2*)&u; }
__device__ __forceinline__ float h2sum(__half2 h) {
    float2 f = __half22float2(h);
    return f.x + f.y;
}
__device__ __forceinline__ void ldsm4(unsigned& r0, unsigned& r1, unsigned& r2,
                                      unsigned& r3, unsigned addr) {
    asm volatile("ldmatrix.sync.aligned.m8n8.x4.shared.b16 {%0,%1,%2,%3}, [%4];"
                 : "=r"(r0), "=r"(r1), "=r"(r2), "=r"(r3) : "r"(addr));
}
__device__ __forceinline__ void ldsm4t(unsigned& r0, unsigned& r1, unsigned& r2,
                                       unsigned& r3, unsigned addr) {
    asm volatile("ldmatrix.sync.aligned.m8n8.x4.trans.shared.b16 {%0,%1,%2,%3}, [%4];"
                 : "=r"(r0), "=r"(r1), "=r"(r2), "=r"(r3) : "r"(addr));
}
__device__ __forceinline__ void mma16816(float* c, const unsigned* a, unsigned b0,
                                         unsigned b1) {
    asm volatile(
        "mma.sync.aligned.m16n8k16.row.col.f32.f16.f16.f32 "
        "{%0,%1,%2,%3}, {%4,%5,%6,%7}, {%8,%9}, {%0,%1,%2,%3};"
        : "+f"(c[0]), "+f"(c[1]), "+f"(c[2]), "+f"(c[3])
        : "r"(a[0]), "r"(a[1]), "r"(a[2]), "r"(a[3]), "r"(b0), "r"(b1));
}
__device__ __forceinline__ void bulk_cp(unsigned dst, const void* src, unsigned bytes,
                                        unsigned mbar) {
    asm volatile(
        "cp.async.bulk.shared::cluster.global.mbarrier::complete_tx::bytes "
        "[%0], [%1], %2, [%3];"
        :: "r"(dst), "l"(src), "r"(bytes), "r"(mbar) : "memory");
}
__device__ __forceinline__ void mbar_expect(unsigned mbar, unsigned bytes) {
    asm volatile("mbarrier.arrive.expect_tx.shared.b64 _, [%0], %1;"
                 :: "r"(mbar), "r"(bytes) : "memory");
}
__device__ __forceinline__ void mbar_wait(unsigned mbar, int phase) {
    asm volatile(
        "{\n\t.reg .pred P;\n\t"
        "W_%=:\n\t"
        "mbarrier.try_wait.parity.acquire.cta.shared::cta.b64 P, [%0], %1, 0x989680;\n\t"
        "@P bra.uni D_%=;\n\t"
        "bra.uni W_%=;\n\t"
        "D_%=:\n\t}"
        :: "r"(mbar), "r"(phase) : "memory");
}
__device__ __forceinline__ void cpa16(unsigned dst, const void* src) {
    asm volatile("cp.async.ca.shared.global [%0], [%1], 16;" :: "r"(dst), "l"(src));
}

// ---------------------------------------------------------------------------
// fp32 -> fp16 convert into PRE-TILED images matching gemm smem stage layout.
// ---------------------------------------------------------------------------
__global__ __launch_bounds__(256) void convert_kernel(const float* __restrict__ dec,
                                                      const float* __restrict__ enc,
                                                      const float* __restrict__ W1,
                                                      const float* __restrict__ W2) {
    int g = blockIdx.x * 256 + threadIdx.x;
    __half* dsth = (__half*)g_h16;
    const float* src;
    size_t off;
    if (g < 262144) {  // A groups
        int chunk = g & 3, row = (g >> 2) & 63, k0 = (g >> 8) & 15;
        int im = (g >> 12) & 31, z = g >> 17;
        src = (z ? enc : dec) + ((im * 64 + row) * DM + k0 * 32 + chunk * 8);
        off = (size_t)z * A_Z_H + (im * 16 + k0) * A_TILE_H + row * APITCH + chunk * 8;
    } else {  // B groups
        int h = g - 262144;
        int chunk = h & 15, row = (h >> 4) & 31, k0 = (h >> 9) & 15;
        int in = (h >> 13) & 1, z = h >> 14;
        src = (z ? W2 : W1) + ((k0 * 32 + row) * SRC + in * 128 + chunk * 8);
        off = A_TOT_H + (size_t)z * B_Z_H + (in * 16 + k0) * B_TILE_H + row * BPITCH +
              chunk * 8;
    }
    float4 v0 = ((const float4*)src)[0];
    float4 v1 = ((const float4*)src)[1];
    __half2 h0 = __floats2half2_rn(v0.x, v0.y);
    __half2 h1 = __floats2half2_rn(v0.z, v0.w);
    __half2 h2 = __floats2half2_rn(v1.x, v1.y);
    __half2 h3 = __floats2half2_rn(v1.z, v1.w);
    *(uint4*)(dsth + off) = make_uint4(*(unsigned*)&h0, *(unsigned*)&h1,
                                       *(unsigned*)&h2, *(unsigned*)&h3);
}

// ---------------------------------------------------------------------------
// Tensor-core GEMM, cp.async.bulk 6-stage mbarrier pipeline (unchanged).
// ---------------------------------------------------------------------------
__global__ __launch_bounds__(256) void gemm_kernel() {
    extern __shared__ __half sm_h[];
    __shared__ unsigned long long mbar[STAGES];
    int z = blockIdx.z;
    const __half* Abase = (const __half*)g_h16 + (size_t)z * A_Z_H +
                          blockIdx.x * 16 * A_TILE_H;
    const __half* Bbase = (const __half*)g_h16 + A_TOT_H + (size_t)z * B_Z_H +
                          blockIdx.y * 16 * B_TILE_H;
    unsigned* C = z ? g_et : g_dt;
    int tid = threadIdx.x;
    int warp = tid >> 5, lane = tid & 31;
    int warp_m = warp >> 2, warp_n = warp & 3;
    int bm = blockIdx.x * 64, bn = blockIdx.y * 128;

    unsigned smem_u32 = (unsigned)__cvta_generic_to_shared(sm_h);
    unsigned mbar_u32 = (unsigned)__cvta_generic_to_shared(mbar);

    if (tid == 0) {
#pragma unroll
        for (int s = 0; s < STAGES; s++)
            asm volatile("mbarrier.init.shared.b64 [%0], 1;"
                         :: "r"(mbar_u32 + 8 * s) : "memory");
        asm volatile("fence.proxy.async.shared::cta;" ::: "memory");
    }
    __syncthreads();
    if (tid == 0) {
#pragma unroll
        for (int s = 0; s < STAGES; s++) {
            unsigned mb = mbar_u32 + 8 * s;
            unsigned so = smem_u32 + s * STAGE_BYTES;
            mbar_expect(mb, STAGE_BYTES);
            bulk_cp(so, Abase + s * A_TILE_H, A_TILE_H * 2, mb);
            bulk_cp(so + A_TILE_H * 2, Bbase + s * B_TILE_H, B_TILE_H * 2, mb);
        }
    }

    int lm_r = lane & 15, lm_c = (lane >> 4) * 8;
    unsigned a_lm = smem_u32 + ((warp_m * 32 + lm_r) * APITCH + lm_c) * 2;
    unsigned b_lm = smem_u32 + (64 * APITCH + lm_r * BPITCH + warp_n * 32 + lm_c) * 2;

    float acc[2][4][4] = {};
    int st = 0, ph = 0;
    for (int it = 0; it < NITER; it++) {
        mbar_wait(mbar_u32 + 8 * st, ph);
        unsigned so = (unsigned)st * STAGE_BYTES;
#pragma unroll
        for (int ks = 0; ks < 2; ks++) {
            unsigned a0[4], a1[4], b0[4], b1[4];
            ldsm4(a0[0], a0[1], a0[2], a0[3], a_lm + so + ks * 32);
            ldsm4(a1[0], a1[1], a1[2], a1[3], a_lm + so + ks * 32 + 16 * APITCH * 2);
            ldsm4t(b0[0], b0[1], b0[2], b0[3], b_lm + so + ks * 16 * BPITCH * 2);
            ldsm4t(b1[0], b1[1], b1[2], b1[3], b_lm + so + ks * 16 * BPITCH * 2 + 32);
            mma16816(acc[0][0], a0, b0[0], b0[1]);
            mma16816(acc[0][1], a0, b0[2], b0[3]);
            mma16816(acc[0][2], a0, b1[0], b1[1]);
            mma16816(acc[0][3], a0, b1[2], b1[3]);
            mma16816(acc[1][0], a1, b0[0], b0[1]);
            mma16816(acc[1][1], a1, b0[2], b0[3]);
            mma16816(acc[1][2], a1, b1[0], b1[1]);
            mma16816(acc[1][3], a1, b1[2], b1[3]);
        }
        __syncthreads();
        int nxt = it + STAGES;
        if (tid == 0 && nxt < NITER) {
            unsigned mb = mbar_u32 + 8 * st;
            unsigned sd = smem_u32 + st * STAGE_BYTES;
            mbar_expect(mb, STAGE_BYTES);
            bulk_cp(sd, Abase + nxt * A_TILE_H, A_TILE_H * 2, mb);
            bulk_cp(sd + A_TILE_H * 2, Bbase + nxt * B_TILE_H, B_TILE_H * 2, mb);
        }
        if (++st == STAGES) { st = 0; ph ^= 1; }
    }
#pragma unroll
    for (int rt = 0; rt < 2; rt++) {
        int r0 = bm + warp_m * 32 + rt * 16 + (lane >> 2);
#pragma unroll
        for (int ct = 0; ct < 4; ct++) {
            int colpair = (bn + warp_n * 32 + ct * 8) / 2 + (lane & 3);
            __half2 h01 = __floats2half2_rn(acc[rt][ct][0], acc[rt][ct][1]);
            __half2 h23 = __floats2half2_rn(acc[rt][ct][2], acc[rt][ct][3]);
            C[r0 * (SRC / 2) + colpair] = *(unsigned*)&h01;
            C[(r0 + 8) * (SRC / 2) + colpair] = *(unsigned*)&h23;
        }
    }
}

// ---------------------------------------------------------------------------
// FUSED scores + masked log_softmax + transpose.
// Block = (b, 8-t-row tile); 256 threads = 8 warps, warp w owns t = t0+w.
// Thread (w, tx) owns s = tx + 32j, j=0..7 over full s row.
// et streamed in 4 double-buffered cp.async chunks of 64 l-values (32KB).
// ---------------------------------------------------------------------------
__global__ __launch_bounds__(256) void fused_kernel(const float* __restrict__ vt,
                                                    const int* __restrict__ lens,
                                                    float* __restrict__ out) {
    extern __shared__ unsigned shm[];
    unsigned* s_et = shm;                       // [2][256][EPW]
    unsigned* s_dt = shm + 2 * EBUF;            // [8][132]
    unsigned* s_vt = s_dt + DTW;                // [128]
    float*    s_o  = (float*)(s_vt + 128);      // [8][OPW]
    int tid = threadIdx.x;
    int tx = tid & 31, w = tid >> 5;
    int b = blockIdx.y, t0 = blockIdx.x * 8;
    const unsigned* dtp = g_dt + (b * TGT + t0) * 128;
    const unsigned* etp = g_et + b * SRC * 128;
    unsigned et_u32 = (unsigned)__cvta_generic_to_shared(s_et);

    // dt tile: 8 rows x 32 uint4, one per thread
    *(uint4*)&s_dt[w * 132 + tx * 4] = *(const uint4*)&dtp[w * 128 + tx * 4];
    // vt -> half2
    if (tid < 128) {
        __half2 h = __floats2half2_rn(vt[2 * tid], vt[2 * tid + 1]);
        s_vt[tid] = *(unsigned*)&h;
    }

#define ET_LOAD(buf, c)                                                       \
    {                                                                         \
        _Pragma("unroll") for (int i = 0; i < 8; i++) {                       \
            int idx = tid + i * 256;                                          \
            int r = idx >> 3, q = idx & 7;                                    \
            cpa16(et_u32 + ((buf) * EBUF + r * EPW + q * 4) * 4,              \
                  etp + r * 128 + (c) * 32 + q * 4);                          \
        }                                                                     \
        asm volatile("cp.async.commit_group;");                               \
    }

    ET_LOAD(0, 0);
    asm volatile("cp.async.wait_group 0;");
    __syncthreads();

    float accf[8] = {};
    for (int c = 0; c < 4; c++) {
        if (c < 3) ET_LOAD((c + 1) & 1, c + 1);
        __half2 acch[8];
#pragma unroll
        for (int j = 0; j < 8; j++) acch[j] = __float2half2_rn(0.f);
        const uint4* dt4 = (const uint4*)&s_dt[w * 132];
        const uint4* vt4 = (const uint4*)s_vt;
        const unsigned* eb = s_et + (c & 1) * EBUF;
#pragma unroll
        for (int u = 0; u < 8; u++) {
            uint4 dv = dt4[c * 8 + u];
            uint4 vv = vt4[c * 8 + u];
#pragma unroll
            for (int j = 0; j < 8; j++) {
                uint4 ev = *(const uint4*)&eb[(tx + 32 * j) * EPW + u * 4];
#define STEP(U)                                                               \
    acch[j] = __hfma2(tanh2(__hadd2(uh(dv.U), uh(ev.U))), uh(vv.U), acch[j]);
                STEP(x) STEP(y) STEP(z) STEP(w)
#undef STEP
            }
        }
#pragma unroll
        for (int j = 0; j < 8; j++) accf[j] += h2sum(acch[j]);
        if (c < 3) asm volatile("cp.async.wait_group 0;");
        __syncthreads();
    }

    // masked log-softmax over s within the warp (scores bounded, skip max)
    int len = lens[b];
    float sum = 0.f;
#pragma unroll
    for (int j = 0; j < 8; j++) {
        if (tx + 32 * j >= len) accf[j] += LOGEPS;
        sum += __expf(accf[j]);
    }
#pragma unroll
    for (int o = 16; o; o >>= 1) sum += __shfl_xor_sync(0xffffffffu, sum, o);
    float lse = logf(sum);
#pragma unroll
    for (int j = 0; j < 8; j++) s_o[w * OPW + tx + 32 * j] = accf[j] - lse;
    __syncthreads();

    // transposed store: out[b][s][t0 + t]
    float* op = out + b * SRC * TGT;
#pragma unroll
    for (int i = 0; i < 8; i++) {
        int idx = tid + i * 256;
        int t = idx & 7, s = idx >> 3;
        op[s * TGT + t0 + t] = s_o[t * OPW + s];
    }
#undef ET_LOAD
}

extern "C" void kernel_launch(void* const* d_in, const int* in_sizes, int n_in,
                              void* d_out, int out_size) {
    const float* dec  = (const float*)d_in[0];
    const float* enc  = (const float*)d_in[1];
    const int*   lens = (const int*)d_in[2];
    const float* W1   = (const float*)d_in[3];
    const float* W2   = (const float*)d_in[4];
    const float* vt   = (const float*)d_in[5];
    float*       out  = (float*)d_out;

    convert_kernel<<<1152, 256>>>(dec, enc, W1, W2);

    constexpr int GEMM_SMEM = STAGES * STAGE_BYTES;  // 82944 B
    cudaFuncSetAttribute(gemm_kernel, cudaFuncAttributeMaxDynamicSharedMemorySize,
                         GEMM_SMEM);
    gemm_kernel<<<dim3(32, 2, 2), 256, GEMM_SMEM>>>();

    cudaFuncSetAttribute(fused_kernel, cudaFuncAttributeMaxDynamicSharedMemorySize,
                         FUSED_SMEM);
    fused_kernel<<<dim3(32, 8), 256, FUSED_SMEM>>>(vt, lens, out);
}